// round 15
// baseline (speedup 1.0000x reference)
#include <cuda_runtime.h>
#include <cuda_fp16.h>
#include <math.h>
#include <stdint.h>

#define B_    2
#define C_    105
#define L_IN  5500
#define NCH   210
#define D_    512
#define L0_   1831
#define T_    56
#define KCODES 1014
#define SECT  (B_*D_*T_)
#define WSL   262144            // one 512x512 weight k-slice (elements, 2^18)

// plane-row capacities (consumer reads up to t0+NT+1 rows)
#define TH0   968
#define TH1   484
#define TH2   292
#define TH3   196
#define TH4   66

// ---------------- device scratch (allocation-free) ----------------
__device__ __align__(128) __half  g_hiA[(size_t)NCH * 64 * TH0 * 16];
__device__ __align__(128) __half  g_loA[(size_t)NCH * 64 * TH0 * 16];
__device__ __align__(128) __half  g_hiB[(size_t)NCH * 64 * TH1 * 16];
__device__ __align__(128) __half  g_loB[(size_t)NCH * 64 * TH1 * 16];
__device__ __align__(128) float   g_c5 [(size_t)NCH * D_ * T_];
__device__ __align__(128) __half  g_wh[14 * WSL];

// ---------------- helpers ----------------
__device__ __forceinline__ float gelu_exact(float v) {
    return 0.5f * v * (1.0f + erff(v * 0.70710678118654752f));
}
__device__ __forceinline__ uint32_t s2u(const void* p) {
    uint32_t a;
    asm("{ .reg .u64 t; cvta.to.shared.u64 t, %1; cvt.u32.u64 %0, t; }" : "=r"(a) : "l"(p));
    return a;
}
__device__ __forceinline__ void mb_init(uint32_t a, uint32_t c) {
    asm volatile("mbarrier.init.shared.b64 [%0], %1;" :: "r"(a), "r"(c) : "memory");
}
__device__ __forceinline__ void mb_expect(uint32_t a, uint32_t bytes) {
    asm volatile("mbarrier.arrive.expect_tx.shared.b64 _, [%0], %1;" :: "r"(a), "r"(bytes) : "memory");
}
__device__ __forceinline__ void mb_arrive(uint32_t a) {
    asm volatile("mbarrier.arrive.shared.b64 _, [%0];" :: "r"(a) : "memory");
}
__device__ __forceinline__ void mb_wait(uint32_t a, uint32_t par) {
    asm volatile("{\n\t.reg .pred P;\n\tWL%=:\n\t"
                 "mbarrier.try_wait.parity.acquire.cta.shared::cta.b64 P, [%0], %1, 0x989680;\n\t"
                 "@!P bra WL%=;\n\t}" :: "r"(a), "r"(par) : "memory");
}
__device__ __forceinline__ void bulk_cp(uint32_t dst, const void* src, uint32_t sz, uint32_t mb) {
    asm volatile("cp.async.bulk.shared::cta.global.mbarrier::complete_tx::bytes [%0], [%1], %2, [%3];"
                 :: "r"(dst), "l"(src), "r"(sz), "r"(mb) : "memory");
}
#define FENCE_ASYNC() asm volatile("fence.proxy.async.shared::cta;" ::: "memory")
__device__ __forceinline__ void ldsm4(uint32_t* r, uint32_t a) {
    asm volatile("ldmatrix.sync.aligned.m8n8.x4.shared.b16 {%0,%1,%2,%3}, [%4];"
                 : "=r"(r[0]), "=r"(r[1]), "=r"(r[2]), "=r"(r[3]) : "r"(a));
}
__device__ __forceinline__ void mma_f16(float* c, const uint32_t* a, uint32_t b0, uint32_t b1) {
    asm volatile("mma.sync.aligned.m16n8k16.row.col.f32.f16.f16.f32 "
        "{%0,%1,%2,%3}, {%4,%5,%6,%7}, {%8,%9}, {%0,%1,%2,%3};"
        : "+f"(c[0]), "+f"(c[1]), "+f"(c[2]), "+f"(c[3])
        : "r"(a[0]), "r"(a[1]), "r"(a[2]), "r"(a[3]), "r"(b0), "r"(b1));
}

// act address (bytes) for element (n, plane value cv, phys index i)
__device__ __forceinline__ size_t act_off(int n, int cv, int i, int Th) {
    int row = i >> 1, p = i & 1;
    int c = cv >> 4, g = (cv >> 3) & 1;
    int sw = g ^ ((row >> 2) & 1);
    return (((size_t)(n * 32 + c) * 2 + p) * Th + row) * 32 + sw * 16 + (cv & 7) * 2;
}

// ---------- fused conv0 + GroupNorm + GELU + split (sliding-window t-loop) ----------
__global__ __launch_bounds__(256) void conv0_fused(
    const float* __restrict__ x, const float* __restrict__ W0,
    const float* __restrict__ g0, const float* __restrict__ b0,
    __half* __restrict__ hi, __half* __restrict__ lo)
{
    __shared__ float xs[L_IN + 8];
    __shared__ float r1[8][32], r2[8][32];
    const int n = blockIdx.y, tid = threadIdx.x;
    const int lane = tid & 31, wid = tid >> 5;
    const int co = blockIdx.x * 32 + lane;

    float w[10];
#pragma unroll
    for (int k = 0; k < 10; ++k) w[k] = W0[co * 10 + k];
    const float* xr = x + (size_t)n * L_IN;
    for (int i = tid; i < L_IN; i += 256) xs[i] = xr[i];
    if (tid < 8) xs[L_IN + tid] = 0.f;
    __syncthreads();

    const int CH   = (L0_ + 7) / 8;
    const int tbeg = wid * CH;
    const int tend = (tbeg + CH < L0_) ? (tbeg + CH) : L0_;

    float lsum = 0.f, lsq = 0.f;
    {
        float xw[10];
#pragma unroll
        for (int j = 0; j < 10; ++j) xw[j] = xs[3 * tbeg + j];
        for (int t = tbeg; t < tend; ++t) {
            float s = 0.f;
#pragma unroll
            for (int k = 0; k < 10; ++k) s += xw[k] * w[k];
            lsum += s; lsq += s * s;
#pragma unroll
            for (int j = 0; j < 7; ++j) xw[j] = xw[j + 3];
            xw[7] = xs[3 * t + 10]; xw[8] = xs[3 * t + 11]; xw[9] = xs[3 * t + 12];
        }
    }
    r1[wid][lane] = lsum; r2[wid][lane] = lsq;
    __syncthreads();
    float tot = 0.f, tsq = 0.f;
#pragma unroll
    for (int i = 0; i < 8; ++i) { tot += r1[i][lane]; tsq += r2[i][lane]; }
    const float mu  = tot * (1.0f / L0_);
    const float var = tsq * (1.0f / L0_) - mu * mu;
    const float sc  = rsqrtf(var + 1e-5f) * g0[co];
    const float sh  = b0[co] - mu * sc;

    {
        float xw[10];
#pragma unroll
        for (int j = 0; j < 10; ++j) xw[j] = xs[3 * tbeg + j];
        for (int t = tbeg; t < tend; ++t) {
            float s = 0.f;
#pragma unroll
            for (int k = 0; k < 10; ++k) s += xw[k] * w[k];
            float v = gelu_exact(s * sc + sh);
            __half h = __float2half(v);
            size_t off = act_off(n, co, t, TH0);
            *(__half*)((char*)hi + off) = h;
            *(__half*)((char*)lo + off) = __float2half(v - __half2float(h));
#pragma unroll
            for (int j = 0; j < 7; ++j) xw[j] = xw[j + 3];
            xw[7] = xs[3 * t + 10]; xw[8] = xs[3 * t + 11]; xw[9] = xs[3 * t + 12];
        }
    }
}

// ---------- ALL weights fp32 [co][ci][kw] -> single fp16 swizzled tiles ----------
__global__ void prep_w_all(
    const float* __restrict__ W1, const float* __restrict__ W2,
    const float* __restrict__ W3, const float* __restrict__ W4,
    const float* __restrict__ W5, __half* __restrict__ wh)
{
    int idx = blockIdx.x * 256 + threadIdx.x;
    if (idx >= 14 * WSL) return;
    int s = idx >> 18, r = idx & (WSL - 1);
    int co = r >> 9, ci = r & 511;
    const float* W; int k, KW;
    if      (s < 3)  { W = W1; k = s;      KW = 3; }
    else if (s < 6)  { W = W2; k = s - 3;  KW = 3; }
    else if (s < 9)  { W = W3; k = s - 6;  KW = 3; }
    else if (s < 12) { W = W4; k = s - 9;  KW = 3; }
    else             { W = W5; k = s - 12; KW = 2; }
    float v = W[(size_t)(co * 512 + ci) * KW + k];
    int sw = ((ci >> 3) & 1) ^ ((co >> 2) & 1);
    size_t off = ((size_t)(s * 32 + (ci >> 4)) * 512 + co) * 32 + sw * 16 + (ci & 7) * 2;
    *(__half*)((char*)wh + off) = __float2half(v);
}

// ---------- conv layer: G=2 n-batched, 3-deep bulk pipeline, fp16x2 HMMA ----------
// CTA: 128co x NTt x 2n. 8 warps 4m x 2n-warp (warp 32co x NT/2 t, both g).
// Stage = one ci16 chunk: 1 weight tile (shared by both n) + 2 act tiles.
template<int KW, int NT, bool FP32OUT>
__global__ __launch_bounds__(256, 2) void conv_bulk(
    const __half* __restrict__ xh, const __half* __restrict__ xl,
    const __half* __restrict__ wt,
    void* __restrict__ outA, __half* __restrict__ outLo,
    int Lin, int Lout, int ThIn, int ThOut)
{
    extern __shared__ __align__(128) char smem[];
    constexpr int ROWS_E = NT + (KW == 3 ? 1 : 0);
    constexpr int ROWS_O = NT;
    constexpr int OFF_B  = KW * 4096;
    constexpr int ACT    = 2 * (ROWS_E + ROWS_O) * 32;   // one g's act block
    constexpr int BUF    = OFF_B + 2 * ACT;
    constexpr int NN     = NT / 16;
    constexpr int NB     = NT / 32;
    const int tid = threadIdx.x, lane = tid & 31, wid = tid >> 5;
    const int wm = wid >> 1, wn = wid & 1;
    const int n0 = blockIdx.z * 2, co0 = blockIdx.y * 128, t0 = blockIdx.x * NT;
    const uint32_t sb  = s2u(smem);
    const uint32_t mbF = sb + 3 * BUF;
    const uint32_t mbE = mbF + 24;

    float acc[2][2][NN][4];
#pragma unroll
    for (int g = 0; g < 2; ++g)
#pragma unroll
        for (int m = 0; m < 2; ++m)
#pragma unroll
            for (int nn = 0; nn < NN; ++nn)
#pragma unroll
                for (int i = 0; i < 4; ++i) acc[g][m][nn][i] = 0.f;

    auto load_stage = [&](int s, int slot) {
        const uint32_t bufb = sb + (uint32_t)slot * BUF;
        const uint32_t mb = mbF + (uint32_t)slot * 8;
        mb_expect(mb, (uint32_t)(KW * 4096 + 2 * ACT));
#pragma unroll
        for (int k = 0; k < KW; ++k) {
            size_t wo = ((size_t)(k * 32 + s) * 512 + co0) * 32;
            bulk_cp(bufb + k * 4096, (const char*)wt + wo, 4096, mb);
        }
#pragma unroll
        for (int g = 0; g < 2; ++g) {
            const uint32_t ab = bufb + OFF_B + g * ACT;
            size_t be = (((size_t)((n0 + g) * 32 + s) * 2 + 0) * ThIn + t0) * 32;
            size_t bo = (((size_t)((n0 + g) * 32 + s) * 2 + 1) * ThIn + t0) * 32;
            bulk_cp(ab,                                  (const char*)xh + be, ROWS_E * 32, mb);
            bulk_cp(ab + ROWS_E * 32,                    (const char*)xl + be, ROWS_E * 32, mb);
            bulk_cp(ab + 2 * ROWS_E * 32,                (const char*)xh + bo, ROWS_O * 32, mb);
            bulk_cp(ab + 2 * ROWS_E * 32 + ROWS_O * 32,  (const char*)xl + bo, ROWS_O * 32, mb);
        }
    };

    if (tid == 0) {
#pragma unroll
        for (int i = 0; i < 3; ++i) { mb_init(mbF + 8 * i, 1); mb_init(mbE + 8 * i, 8); }
    }
    __syncthreads();
    if (tid == 0) { FENCE_ASYNC(); load_stage(0, 0); load_stage(1, 1); load_stage(2, 2); }

    const int laneR = lane & 15, gsel = lane >> 4;
    int slot = 0, fph = 0;
    for (int s = 0; s < 32; ++s) {
        mb_wait(mbF + 8u * slot, fph);
        const uint32_t bufb = sb + (uint32_t)slot * BUF;
#pragma unroll
        for (int k = 0; k < KW; ++k) {
            uint32_t ah[2][4];
#pragma unroll
            for (int m = 0; m < 2; ++m) {
                int r = wm * 32 + m * 16 + laneR;
                uint32_t a = bufb + k * 4096 + r * 32 + ((gsel ^ ((r >> 2) & 1)) << 4);
                ldsm4(ah[m], a);
            }
            const int p = k & 1, kd = k >> 1;
#pragma unroll
            for (int g = 0; g < 2; ++g) {
                const uint32_t ab = bufb + OFF_B + g * ACT;
                const uint32_t baseh = ab + (p ? 2 * ROWS_E * 32 : 0);
                const uint32_t rsz = (p ? ROWS_O : ROWS_E) * 32;
#pragma unroll
                for (int b = 0; b < NB; ++b) {
                    int r = wn * (NT / 2) + b * 16 + laneR + kd;
                    uint32_t aB = baseh + r * 32 + ((gsel ^ ((r >> 2) & 1)) << 4);
                    uint32_t bh[4], bl[4];
                    ldsm4(bh, aB);
                    ldsm4(bl, aB + rsz);
#pragma unroll
                    for (int m = 0; m < 2; ++m)
#pragma unroll
                        for (int o = 0; o < 2; ++o)
                            mma_f16(acc[g][m][b * 2 + o], ah[m], bh[o], bh[o + 2]);
#pragma unroll
                    for (int m = 0; m < 2; ++m)
#pragma unroll
                        for (int o = 0; o < 2; ++o)
                            mma_f16(acc[g][m][b * 2 + o], ah[m], bl[o], bl[o + 2]);
                }
            }
        }
        __syncwarp();
        if (lane == 0) mb_arrive(mbE + 8u * slot);
        if (tid == 0 && s + 3 < 32) {
            mb_wait(mbE + 8u * slot, (uint32_t)((s / 3) & 1));
            load_stage(s + 3, slot);
        }
        if (++slot == 3) { slot = 0; fph ^= 1; }
    }
    __syncthreads();

    if (FP32OUT) {
        float* outF = (float*)outA;
#pragma unroll
        for (int g = 0; g < 2; ++g) {
#pragma unroll
            for (int m = 0; m < 2; ++m) {
                const int coA = co0 + wm * 32 + m * 16 + (lane >> 2);
#pragma unroll
                for (int nn = 0; nn < NN; ++nn) {
                    int tt = t0 + wn * (NT / 2) + nn * 8 + 2 * (lane & 3);
#pragma unroll
                    for (int i = 0; i < 4; ++i) {
                        int t = tt + (i & 1), co = coA + (i >> 1) * 8;
                        if (t < Lout)
                            outF[((size_t)(n0 + g) * D_ + co) * T_ + t] = gelu_exact(acc[g][m][nn][i]);
                    }
                }
            }
        }
    } else {
        __half* sHi = (__half*)smem;
        __half* sLo = (__half*)(smem + NT * 272);
        for (int g = 0; g < 2; ++g) {
#pragma unroll
            for (int m = 0; m < 2; ++m) {
                const int coA = wm * 32 + m * 16 + (lane >> 2);
#pragma unroll
                for (int nn = 0; nn < NN; ++nn) {
                    const int tt = wn * (NT / 2) + nn * 8 + 2 * (lane & 3);
#pragma unroll
                    for (int i = 0; i < 4; ++i) {
                        int t = tt + (i & 1), co = coA + (i >> 1) * 8;
                        float gg = gelu_exact(acc[g][m][nn][i]);
                        __half h = __float2half(gg);
                        sHi[t * 136 + co] = h;
                        sLo[t * 136 + co] = __float2half(gg - __half2float(h));
                    }
                }
            }
            __syncthreads();
            for (int idx = tid; idx < NT * 16; idx += 256) {
                int t = idx >> 4, gp = idx & 15;
                int tAbs = t0 + t;
                if (tAbs < Lout) {
                    int row = tAbs >> 1, p = tAbs & 1;
                    int coA = co0 + gp * 8;
                    int c = coA >> 4, gb = (coA >> 3) & 1;
                    int sw = gb ^ ((row >> 2) & 1);
                    size_t off = (((size_t)((n0 + g) * 32 + c) * 2 + p) * ThOut + row) * 32 + sw * 16;
                    *(uint4*)((char*)outA + off)  = *(uint4*)(smem + t * 272 + gp * 16);
                    *(uint4*)((char*)outLo + off) = *(uint4*)(smem + NT * 272 + t * 272 + gp * 16);
                }
            }
            __syncthreads();
        }
    }
}

// ---------- 1x1 channel fusion ----------
__global__ void fusion_kernel(const float* __restrict__ h, const float* __restrict__ fw,
                              const float* __restrict__ fb, float* __restrict__ ze)
{
    int idx = blockIdx.x * 256 + threadIdx.x;
    if (idx >= SECT) return;
    int b = idx / (D_ * T_);
    int r = idx - b * (D_ * T_);
    float s = fb[0];
    const float* hp = h + (size_t)b * C_ * D_ * T_ + r;
#pragma unroll 5
    for (int c = 0; c < C_; ++c) s += hp[(size_t)c * D_ * T_] * fw[c];
    ze[idx] = s;
}

// ---------- VQ argmin ----------
__global__ __launch_bounds__(256) void quantize_kernel(
    const float* __restrict__ ze, const float* __restrict__ cb, float* __restrict__ out)
{
    __shared__ __align__(16) float z[512];
    __shared__ float sd[256];
    __shared__ int   si[256];
    const int blk = blockIdx.x;
    const int b = blk / T_, t = blk - b * T_;
    const int tid = threadIdx.x;

    const float* zb = ze + (size_t)b * D_ * T_ + t;
    for (int d = tid; d < D_; d += 256) z[d] = zb[(size_t)d * T_];
    __syncthreads();

    float best = 3.4e38f; int bi = 0;
    for (int kk = tid; kk < KCODES; kk += 256) {
        const float4* cr = reinterpret_cast<const float4*>(cb + (size_t)kk * D_);
        const float4* zr = reinterpret_cast<const float4*>(z);
        float s = 0.f;
#pragma unroll 8
        for (int q = 0; q < 128; ++q) {
            float4 c4 = cr[q], z4 = zr[q];
            float d0 = z4.x - c4.x, d1 = z4.y - c4.y;
            float d2 = z4.z - c4.z, d3 = z4.w - c4.w;
            s += d0 * d0 + d1 * d1 + d2 * d2 + d3 * d3;
        }
        if (s < best) { best = s; bi = kk; }
    }
    sd[tid] = best; si[tid] = bi;
    __syncthreads();
    for (int off = 128; off; off >>= 1) {
        if (tid < off) {
            float od = sd[tid + off]; int oi = si[tid + off];
            if (od < sd[tid] || (od == sd[tid] && oi < si[tid])) { sd[tid] = od; si[tid] = oi; }
        }
        __syncthreads();
    }
    const int w = si[0];
    const float* crow = cb + (size_t)w * D_;
    const size_t base = (size_t)b * D_ * T_ + t;
    for (int d = tid; d < D_; d += 256) {
        float v = crow[d];
        out[base + (size_t)d * T_]            = v;
        out[2 * SECT + base + (size_t)d * T_] = v;
    }
}

// ---------- launch ----------
extern "C" void kernel_launch(void* const* d_in, const int* in_sizes, int n_in,
                              void* d_out, int out_size)
{
    const float* x  = (const float*)d_in[0];
    const float* W0 = (const float*)d_in[4];
    const float* g0 = (const float*)d_in[5];
    const float* b0 = (const float*)d_in[6];
    const float* W1 = (const float*)d_in[7];
    const float* W2 = (const float*)d_in[8];
    const float* W3 = (const float*)d_in[9];
    const float* W4 = (const float*)d_in[10];
    const float* W5 = (const float*)d_in[11];
    const float* fw = (const float*)d_in[12];
    const float* fb = (const float*)d_in[13];
    const float* cb = (const float*)d_in[14];
    float* out = (float*)d_out;

    float* pc5 = nullptr;
    __half *hA, *lA, *hB, *lB, *wh;
    cudaGetSymbolAddress((void**)&pc5, g_c5);
    cudaGetSymbolAddress((void**)&hA,  g_hiA);
    cudaGetSymbolAddress((void**)&lA,  g_loA);
    cudaGetSymbolAddress((void**)&hB,  g_hiB);
    cudaGetSymbolAddress((void**)&lB,  g_loB);
    cudaGetSymbolAddress((void**)&wh,  g_wh);

    // NT=96 KW=3: BUF = 12288 + 2*12352 = 36992; 3-deep + mbarriers
    const int SM96 = 3 * 36992 + 48;                  // 111024 (retile 96*544=52224 fits)
    // NT=64 KW=2: BUF = 8192 + 2*8192 = 24576
    const int SM64 = 3 * 24576 + 48;                  // 73776
    cudaFuncSetAttribute(conv_bulk<3, 96, false>, cudaFuncAttributeMaxDynamicSharedMemorySize, SM96);
    cudaFuncSetAttribute(conv_bulk<2, 64, true>,  cudaFuncAttributeMaxDynamicSharedMemorySize, SM64);

    prep_w_all<<<(14 * WSL + 255) / 256, 256>>>(W1, W2, W3, W4, W5, wh);
    conv0_fused<<<dim3(16, NCH), 256>>>(x, W0, g0, b0, hA, lA);

    conv_bulk<3, 96, false><<<dim3(10, 4, 105), 256, SM96>>>(hA, lA, wh + 0 * WSL, hB, lB, 1831, 915, TH0, TH1);
    conv_bulk<3, 96, false><<<dim3(5, 4, 105), 256, SM96>>>(hB, lB, wh + 3 * WSL, hA, lA, 915, 457, TH1, TH2);
    conv_bulk<3, 96, false><<<dim3(3, 4, 105), 256, SM96>>>(hA, lA, wh + 6 * WSL, hB, lB, 457, 228, TH2, TH3);
    conv_bulk<3, 96, false><<<dim3(2, 4, 105), 256, SM96>>>(hB, lB, wh + 9 * WSL, hA, lA, 228, 113, TH3, TH4);
    conv_bulk<2, 64, true><<<dim3(1, 4, 105), 256, SM64>>>(hA, lA, wh + 12 * WSL, pc5, nullptr, 113, 56, TH4, 0);

    fusion_kernel<<<(SECT + 255) / 256, 256>>>(pc5, fw, fb, out + SECT);
    quantize_kernel<<<B_ * T_, 256>>>(out + SECT, cb, out);
}

// round 16
// speedup vs baseline: 2.9763x; 2.9763x over previous
#include <cuda_runtime.h>
#include <cuda_fp16.h>
#include <math.h>
#include <stdint.h>

#define B_    2
#define C_    105
#define L_IN  5500
#define NCH   210
#define D_    512
#define L0_   1831
#define T_    56
#define KCODES 1014
#define SECT  (B_*D_*T_)
#define WSL   262144            // one 512x512 weight k-slice (elements, 2^18)

// plane-row capacities
#define TH0   968
#define TH1   484
#define TH2   260
#define TH3   132
#define TH4   66

// ---------------- device scratch (allocation-free) ----------------
__device__ __align__(128) __half  g_hiA[(size_t)NCH * 64 * TH0 * 16];
__device__ __align__(128) __half  g_loA[(size_t)NCH * 64 * TH0 * 16];
__device__ __align__(128) __half  g_hiB[(size_t)NCH * 64 * TH1 * 16];
__device__ __align__(128) __half  g_loB[(size_t)NCH * 64 * TH1 * 16];
__device__ __align__(128) float   g_c5 [(size_t)NCH * D_ * T_];
__device__ __align__(128) __half  g_wh[14 * WSL];

// ---------------- helpers ----------------
__device__ __forceinline__ float gelu_exact(float v) {
    return 0.5f * v * (1.0f + erff(v * 0.70710678118654752f));
}
__device__ __forceinline__ uint32_t s2u(const void* p) {
    uint32_t a;
    asm("{ .reg .u64 t; cvta.to.shared.u64 t, %1; cvt.u32.u64 %0, t; }" : "=r"(a) : "l"(p));
    return a;
}
__device__ __forceinline__ void mb_init(uint32_t a, uint32_t c) {
    asm volatile("mbarrier.init.shared.b64 [%0], %1;" :: "r"(a), "r"(c) : "memory");
}
__device__ __forceinline__ void mb_expect(uint32_t a, uint32_t bytes) {
    asm volatile("mbarrier.arrive.expect_tx.shared.b64 _, [%0], %1;" :: "r"(a), "r"(bytes) : "memory");
}
__device__ __forceinline__ void mb_arrive(uint32_t a) {
    asm volatile("mbarrier.arrive.shared.b64 _, [%0];" :: "r"(a) : "memory");
}
__device__ __forceinline__ void mb_wait(uint32_t a, uint32_t par) {
    asm volatile("{\n\t.reg .pred P;\n\tWL%=:\n\t"
                 "mbarrier.try_wait.parity.acquire.cta.shared::cta.b64 P, [%0], %1, 0x989680;\n\t"
                 "@!P bra WL%=;\n\t}" :: "r"(a), "r"(par) : "memory");
}
__device__ __forceinline__ void bulk_cp(uint32_t dst, const void* src, uint32_t sz, uint32_t mb) {
    asm volatile("cp.async.bulk.shared::cta.global.mbarrier::complete_tx::bytes [%0], [%1], %2, [%3];"
                 :: "r"(dst), "l"(src), "r"(sz), "r"(mb) : "memory");
}
#define FENCE_ASYNC() asm volatile("fence.proxy.async.shared::cta;" ::: "memory")
__device__ __forceinline__ void ldsm4(uint32_t* r, uint32_t a) {
    asm volatile("ldmatrix.sync.aligned.m8n8.x4.shared.b16 {%0,%1,%2,%3}, [%4];"
                 : "=r"(r[0]), "=r"(r[1]), "=r"(r[2]), "=r"(r[3]) : "r"(a));
}
__device__ __forceinline__ void mma_f16(float* c, const uint32_t* a, uint32_t b0, uint32_t b1) {
    asm volatile("mma.sync.aligned.m16n8k16.row.col.f32.f16.f16.f32 "
        "{%0,%1,%2,%3}, {%4,%5,%6,%7}, {%8,%9}, {%0,%1,%2,%3};"
        : "+f"(c[0]), "+f"(c[1]), "+f"(c[2]), "+f"(c[3])
        : "r"(a[0]), "r"(a[1]), "r"(a[2]), "r"(a[3]), "r"(b0), "r"(b1));
}

// act address (bytes) for element (n, plane value cv, phys index i)
__device__ __forceinline__ size_t act_off(int n, int cv, int i, int Th) {
    int row = i >> 1, p = i & 1;
    int c = cv >> 4, g = (cv >> 3) & 1;
    int sw = g ^ ((row >> 2) & 1);
    return (((size_t)(n * 32 + c) * 2 + p) * Th + row) * 32 + sw * 16 + (cv & 7) * 2;
}

// ---------- fused conv0 + GroupNorm + GELU + split (sliding-window t-loop) ----------
__global__ __launch_bounds__(256) void conv0_fused(
    const float* __restrict__ x, const float* __restrict__ W0,
    const float* __restrict__ g0, const float* __restrict__ b0,
    __half* __restrict__ hi, __half* __restrict__ lo)
{
    __shared__ float xs[L_IN + 8];
    __shared__ float r1[8][32], r2[8][32];
    const int n = blockIdx.y, tid = threadIdx.x;
    const int lane = tid & 31, wid = tid >> 5;
    const int co = blockIdx.x * 32 + lane;

    float w[10];
#pragma unroll
    for (int k = 0; k < 10; ++k) w[k] = W0[co * 10 + k];
    const float* xr = x + (size_t)n * L_IN;
    for (int i = tid; i < L_IN; i += 256) xs[i] = xr[i];
    if (tid < 8) xs[L_IN + tid] = 0.f;
    __syncthreads();

    const int CH   = (L0_ + 7) / 8;
    const int tbeg = wid * CH;
    const int tend = (tbeg + CH < L0_) ? (tbeg + CH) : L0_;

    float lsum = 0.f, lsq = 0.f;
    {
        float xw[10];
#pragma unroll
        for (int j = 0; j < 10; ++j) xw[j] = xs[3 * tbeg + j];
        for (int t = tbeg; t < tend; ++t) {
            float s = 0.f;
#pragma unroll
            for (int k = 0; k < 10; ++k) s += xw[k] * w[k];
            lsum += s; lsq += s * s;
#pragma unroll
            for (int j = 0; j < 7; ++j) xw[j] = xw[j + 3];
            xw[7] = xs[3 * t + 10]; xw[8] = xs[3 * t + 11]; xw[9] = xs[3 * t + 12];
        }
    }
    r1[wid][lane] = lsum; r2[wid][lane] = lsq;
    __syncthreads();
    float tot = 0.f, tsq = 0.f;
#pragma unroll
    for (int i = 0; i < 8; ++i) { tot += r1[i][lane]; tsq += r2[i][lane]; }
    const float mu  = tot * (1.0f / L0_);
    const float var = tsq * (1.0f / L0_) - mu * mu;
    const float sc  = rsqrtf(var + 1e-5f) * g0[co];
    const float sh  = b0[co] - mu * sc;

    {
        float xw[10];
#pragma unroll
        for (int j = 0; j < 10; ++j) xw[j] = xs[3 * tbeg + j];
        for (int t = tbeg; t < tend; ++t) {
            float s = 0.f;
#pragma unroll
            for (int k = 0; k < 10; ++k) s += xw[k] * w[k];
            float v = gelu_exact(s * sc + sh);
            __half h = __float2half(v);
            size_t off = act_off(n, co, t, TH0);
            *(__half*)((char*)hi + off) = h;
            *(__half*)((char*)lo + off) = __float2half(v - __half2float(h));
#pragma unroll
            for (int j = 0; j < 7; ++j) xw[j] = xw[j + 3];
            xw[7] = xs[3 * t + 10]; xw[8] = xs[3 * t + 11]; xw[9] = xs[3 * t + 12];
        }
    }
}

// ---------- ALL weights fp32 [co][ci][kw] -> single fp16 swizzled tiles ----------
__global__ void prep_w_all(
    const float* __restrict__ W1, const float* __restrict__ W2,
    const float* __restrict__ W3, const float* __restrict__ W4,
    const float* __restrict__ W5, __half* __restrict__ wh)
{
    int idx = blockIdx.x * 256 + threadIdx.x;
    if (idx >= 14 * WSL) return;
    int s = idx >> 18, r = idx & (WSL - 1);
    int co = r >> 9, ci = r & 511;
    const float* W; int k, KW;
    if      (s < 3)  { W = W1; k = s;      KW = 3; }
    else if (s < 6)  { W = W2; k = s - 3;  KW = 3; }
    else if (s < 9)  { W = W3; k = s - 6;  KW = 3; }
    else if (s < 12) { W = W4; k = s - 9;  KW = 3; }
    else             { W = W5; k = s - 12; KW = 2; }
    float v = W[(size_t)(co * 512 + ci) * KW + k];
    int sw = ((ci >> 3) & 1) ^ ((co >> 2) & 1);
    size_t off = ((size_t)(s * 32 + (ci >> 4)) * 512 + co) * 32 + sw * 16 + (ci & 7) * 2;
    *(__half*)((char*)wh + off) = __float2half(v);
}

// ---------- conv layer: 3-deep bulk pipeline, fp16x2 HMMA, B-frag software pipeline ----------
// CTA 128co x NTt, 8 warps 4m x 2n (warp 32co x NT/2 t). 32 stages of ci16.
// Dynamic smem >= max(3*BUF+48, NT*544).
template<int KW, int NT, bool FP32OUT>
__global__ __launch_bounds__(256, 2) void conv_bulk(
    const __half* __restrict__ xh, const __half* __restrict__ xl,
    const __half* __restrict__ wt,
    void* __restrict__ outA, __half* __restrict__ outLo,
    int Lin, int Lout, int ThIn, int ThOut)
{
    extern __shared__ __align__(128) char smem[];
    constexpr int ROWS_E = NT + (KW == 3 ? 1 : 0);
    constexpr int ROWS_O = NT;
    constexpr int OFF_B  = KW * 4096;
    constexpr int BUF    = OFF_B + 2 * (ROWS_E + ROWS_O) * 32;
    constexpr int NN     = NT / 16;
    constexpr int NB     = NT / 32;
    const int tid = threadIdx.x, lane = tid & 31, wid = tid >> 5;
    const int wm = wid >> 1, wn = wid & 1;
    const int n = blockIdx.z, co0 = blockIdx.y * 128, t0 = blockIdx.x * NT;
    const uint32_t sb  = s2u(smem);
    const uint32_t mbF = sb + 3 * BUF;
    const uint32_t mbE = mbF + 24;

    float acc[2][NN][4];
#pragma unroll
    for (int m = 0; m < 2; ++m)
#pragma unroll
        for (int nn = 0; nn < NN; ++nn)
#pragma unroll
            for (int i = 0; i < 4; ++i) acc[m][nn][i] = 0.f;

    auto load_stage = [&](int s, int slot) {
        const uint32_t bufb = sb + (uint32_t)slot * BUF;
        const uint32_t mb = mbF + (uint32_t)slot * 8;
        mb_expect(mb, (uint32_t)(KW * 4096 + 2 * (ROWS_E + ROWS_O) * 32));
#pragma unroll
        for (int k = 0; k < KW; ++k) {
            size_t wo = ((size_t)(k * 32 + s) * 512 + co0) * 32;
            bulk_cp(bufb + k * 4096, (const char*)wt + wo, 4096, mb);
        }
        size_t be = (((size_t)(n * 32 + s) * 2 + 0) * ThIn + t0) * 32;
        size_t bo = (((size_t)(n * 32 + s) * 2 + 1) * ThIn + t0) * 32;
        bulk_cp(bufb + OFF_B,                                  (const char*)xh + be, ROWS_E * 32, mb);
        bulk_cp(bufb + OFF_B + ROWS_E * 32,                    (const char*)xl + be, ROWS_E * 32, mb);
        bulk_cp(bufb + OFF_B + 2 * ROWS_E * 32,                (const char*)xh + bo, ROWS_O * 32, mb);
        bulk_cp(bufb + OFF_B + 2 * ROWS_E * 32 + ROWS_O * 32,  (const char*)xl + bo, ROWS_O * 32, mb);
    };

    if (tid == 0) {
#pragma unroll
        for (int i = 0; i < 3; ++i) { mb_init(mbF + 8 * i, 1); mb_init(mbE + 8 * i, 8); }
    }
    __syncthreads();
    if (tid == 0) { FENCE_ASYNC(); load_stage(0, 0); load_stage(1, 1); load_stage(2, 2); }

    const int laneR = lane & 15, gsel = lane >> 4;
    int slot = 0, fph = 0;
    for (int s = 0; s < 32; ++s) {
        mb_wait(mbF + 8u * slot, fph);
        const uint32_t bufb = sb + (uint32_t)slot * BUF;

        // B-address generator for (k, b)
        auto baddr = [&](int k, int b) -> uint32_t {
            const int p = k & 1, kd = k >> 1;
            const uint32_t baseh = bufb + OFF_B + (p ? 2 * ROWS_E * 32 : 0);
            int r = wn * (NT / 2) + b * 16 + laneR + kd;
            return baseh + r * 32 + ((gsel ^ ((r >> 2) & 1)) << 4);
        };

        uint32_t bh[2][4], bl[2][4];
        {   // preload (k=0, b=0)
            uint32_t a = baddr(0, 0);
            ldsm4(bh[0], a);
            ldsm4(bl[0], a + ROWS_E * 32);
        }
        int cur = 0;
#pragma unroll
        for (int k = 0; k < KW; ++k) {
            uint32_t ah[2][4];
#pragma unroll
            for (int m = 0; m < 2; ++m) {
                int r = wm * 32 + m * 16 + laneR;
                uint32_t a = bufb + k * 4096 + r * 32 + ((gsel ^ ((r >> 2) & 1)) << 4);
                ldsm4(ah[m], a);
            }
#pragma unroll
            for (int b = 0; b < NB; ++b) {
                // prefetch next (k,b) group's B frags before current MMAs
                const int nk = (b + 1 < NB) ? k : k + 1;
                const int nb = (b + 1 < NB) ? b + 1 : 0;
                if (nk < KW) {
                    uint32_t a = baddr(nk, nb);
                    uint32_t rs = ((nk & 1) ? ROWS_O : ROWS_E) * 32;
                    ldsm4(bh[cur ^ 1], a);
                    ldsm4(bl[cur ^ 1], a + rs);
                }
                const uint32_t* BH = bh[cur];
                const uint32_t* BL = bl[cur];
#pragma unroll
                for (int m = 0; m < 2; ++m)
#pragma unroll
                    for (int o = 0; o < 2; ++o)
                        mma_f16(acc[m][b * 2 + o], ah[m], BH[o], BH[o + 2]);
#pragma unroll
                for (int m = 0; m < 2; ++m)
#pragma unroll
                    for (int o = 0; o < 2; ++o)
                        mma_f16(acc[m][b * 2 + o], ah[m], BL[o], BL[o + 2]);
                cur ^= 1;
            }
        }
        __syncwarp();
        if (lane == 0) mb_arrive(mbE + 8u * slot);
        if (tid == 0 && s + 3 < 32) {
            mb_wait(mbE + 8u * slot, (uint32_t)((s / 3) & 1));
            load_stage(s + 3, slot);
        }
        if (++slot == 3) { slot = 0; fph ^= 1; }
    }
    __syncthreads();

    if (FP32OUT) {
        float* outF = (float*)outA;
#pragma unroll
        for (int m = 0; m < 2; ++m) {
            const int coA = co0 + wm * 32 + m * 16 + (lane >> 2);
#pragma unroll
            for (int nn = 0; nn < NN; ++nn) {
                int tt = t0 + wn * (NT / 2) + nn * 8 + 2 * (lane & 3);
#pragma unroll
                for (int i = 0; i < 4; ++i) {
                    int t = tt + (i & 1), co = coA + (i >> 1) * 8;
                    if (t < Lout)
                        outF[((size_t)n * D_ + co) * T_ + t] = gelu_exact(acc[m][nn][i]);
                }
            }
        }
    } else {
        __half* sHi = (__half*)smem;
        __half* sLo = (__half*)(smem + NT * 272);
#pragma unroll
        for (int m = 0; m < 2; ++m) {
            const int coA = wm * 32 + m * 16 + (lane >> 2);
#pragma unroll
            for (int nn = 0; nn < NN; ++nn) {
                const int tt = wn * (NT / 2) + nn * 8 + 2 * (lane & 3);
#pragma unroll
                for (int i = 0; i < 4; ++i) {
                    int t = tt + (i & 1), co = coA + (i >> 1) * 8;
                    float g = gelu_exact(acc[m][nn][i]);
                    __half h = __float2half(g);
                    sHi[t * 136 + co] = h;
                    sLo[t * 136 + co] = __float2half(g - __half2float(h));
                }
            }
        }
        __syncthreads();
        for (int idx = tid; idx < NT * 16; idx += 256) {
            int t = idx >> 4, gg = idx & 15;
            int tAbs = t0 + t;
            if (tAbs < Lout) {
                int row = tAbs >> 1, p = tAbs & 1;
                int coA = co0 + gg * 8;
                int c = coA >> 4, gb = (coA >> 3) & 1;
                int sw = gb ^ ((row >> 2) & 1);
                size_t off = (((size_t)(n * 32 + c) * 2 + p) * ThOut + row) * 32 + sw * 16;
                *(uint4*)((char*)outA + off)  = *(uint4*)(smem + t * 272 + gg * 16);
                *(uint4*)((char*)outLo + off) = *(uint4*)(smem + NT * 272 + t * 272 + gg * 16);
            }
        }
    }
}

// ---------- 1x1 channel fusion ----------
__global__ void fusion_kernel(const float* __restrict__ h, const float* __restrict__ fw,
                              const float* __restrict__ fb, float* __restrict__ ze)
{
    int idx = blockIdx.x * 256 + threadIdx.x;
    if (idx >= SECT) return;
    int b = idx / (D_ * T_);
    int r = idx - b * (D_ * T_);
    float s = fb[0];
    const float* hp = h + (size_t)b * C_ * D_ * T_ + r;
#pragma unroll 5
    for (int c = 0; c < C_; ++c) s += hp[(size_t)c * D_ * T_] * fw[c];
    ze[idx] = s;
}

// ---------- VQ argmin ----------
__global__ __launch_bounds__(256) void quantize_kernel(
    const float* __restrict__ ze, const float* __restrict__ cb, float* __restrict__ out)
{
    __shared__ __align__(16) float z[512];
    __shared__ float sd[256];
    __shared__ int   si[256];
    const int blk = blockIdx.x;
    const int b = blk / T_, t = blk - b * T_;
    const int tid = threadIdx.x;

    const float* zb = ze + (size_t)b * D_ * T_ + t;
    for (int d = tid; d < D_; d += 256) z[d] = zb[(size_t)d * T_];
    __syncthreads();

    float best = 3.4e38f; int bi = 0;
    for (int kk = tid; kk < KCODES; kk += 256) {
        const float4* cr = reinterpret_cast<const float4*>(cb + (size_t)kk * D_);
        const float4* zr = reinterpret_cast<const float4*>(z);
        float s = 0.f;
#pragma unroll 8
        for (int q = 0; q < 128; ++q) {
            float4 c4 = cr[q], z4 = zr[q];
            float d0 = z4.x - c4.x, d1 = z4.y - c4.y;
            float d2 = z4.z - c4.z, d3 = z4.w - c4.w;
            s += d0 * d0 + d1 * d1 + d2 * d2 + d3 * d3;
        }
        if (s < best) { best = s; bi = kk; }
    }
    sd[tid] = best; si[tid] = bi;
    __syncthreads();
    for (int off = 128; off; off >>= 1) {
        if (tid < off) {
            float od = sd[tid + off]; int oi = si[tid + off];
            if (od < sd[tid] || (od == sd[tid] && oi < si[tid])) { sd[tid] = od; si[tid] = oi; }
        }
        __syncthreads();
    }
    const int w = si[0];
    const float* crow = cb + (size_t)w * D_;
    const size_t base = (size_t)b * D_ * T_ + t;
    for (int d = tid; d < D_; d += 256) {
        float v = crow[d];
        out[base + (size_t)d * T_]            = v;
        out[2 * SECT + base + (size_t)d * T_] = v;
    }
}

// ---------- launch ----------
extern "C" void kernel_launch(void* const* d_in, const int* in_sizes, int n_in,
                              void* d_out, int out_size)
{
    const float* x  = (const float*)d_in[0];
    const float* W0 = (const float*)d_in[4];
    const float* g0 = (const float*)d_in[5];
    const float* b0 = (const float*)d_in[6];
    const float* W1 = (const float*)d_in[7];
    const float* W2 = (const float*)d_in[8];
    const float* W3 = (const float*)d_in[9];
    const float* W4 = (const float*)d_in[10];
    const float* W5 = (const float*)d_in[11];
    const float* fw = (const float*)d_in[12];
    const float* fb = (const float*)d_in[13];
    const float* cb = (const float*)d_in[14];
    float* out = (float*)d_out;

    float* pc5 = nullptr;
    __half *hA, *lA, *hB, *lB, *wh;
    cudaGetSymbolAddress((void**)&pc5, g_c5);
    cudaGetSymbolAddress((void**)&hA,  g_hiA);
    cudaGetSymbolAddress((void**)&lA,  g_loA);
    cudaGetSymbolAddress((void**)&hB,  g_hiB);
    cudaGetSymbolAddress((void**)&lB,  g_loB);
    cudaGetSymbolAddress((void**)&wh,  g_wh);

    // smem = max(pipeline: 3*BUF+48, epilogue retile: NT*544)
    const int SM160 = 3 * (3 * 4096 + 2 * (161 + 160) * 32) + 48;  // 98544 > 87040
    const int SM128 = 3 * (3 * 4096 + 2 * (129 + 128) * 32) + 48;  // 86256 > 69632
    const int SM64  = 3 * (2 * 4096 + 2 * (64 + 64) * 32) + 48;    // 49200
    cudaFuncSetAttribute(conv_bulk<3, 160, false>, cudaFuncAttributeMaxDynamicSharedMemorySize, SM160);
    cudaFuncSetAttribute(conv_bulk<3, 128, false>, cudaFuncAttributeMaxDynamicSharedMemorySize, SM128);
    cudaFuncSetAttribute(conv_bulk<2, 64, true>,   cudaFuncAttributeMaxDynamicSharedMemorySize, SM64);

    prep_w_all<<<(14 * WSL + 255) / 256, 256>>>(W1, W2, W3, W4, W5, wh);
    conv0_fused<<<dim3(16, NCH), 256>>>(x, W0, g0, b0, hA, lA);

    conv_bulk<3, 160, false><<<dim3(6, 4, NCH), 256, SM160>>>(hA, lA, wh + 0 * WSL, hB, lB, 1831, 915, TH0, TH1);
    conv_bulk<3, 160, false><<<dim3(3, 4, NCH), 256, SM160>>>(hB, lB, wh + 3 * WSL, hA, lA, 915, 457, TH1, TH2);
    conv_bulk<3, 128, false><<<dim3(2, 4, NCH), 256, SM128>>>(hA, lA, wh + 6 * WSL, hB, lB, 457, 228, TH2, TH3);
    conv_bulk<3, 128, false><<<dim3(1, 4, NCH), 256, SM128>>>(hB, lB, wh + 9 * WSL, hA, lA, 228, 113, TH3, TH4);
    conv_bulk<2, 64, true><<<dim3(1, 4, NCH), 256, SM64>>>(hA, lA, wh + 12 * WSL, pc5, nullptr, 113, 56, TH4, 0);

    fusion_kernel<<<(SECT + 255) / 256, 256>>>(pc5, fw, fb, out + SECT);
    quantize_kernel<<<B_ * T_, 256>>>(out + SECT, cb, out);
}

// round 17
// speedup vs baseline: 4.0406x; 1.3576x over previous
#include <cuda_runtime.h>
#include <cuda_fp16.h>
#include <math.h>
#include <stdint.h>

#define B_    2
#define C_    105
#define L_IN  5500
#define NCH   210
#define D_    512
#define L0_   1831
#define T_    56
#define KCODES 1014
#define SECT  (B_*D_*T_)
#define WSL   262144            // one 512x512 weight k-slice (elements, 2^18)

// plane-row capacities
#define TH0   968
#define TH1   484
#define TH2   260
#define TH3   132
#define TH4   66

// ---------------- device scratch (allocation-free) ----------------
__device__ __align__(128) __half  g_hiA[(size_t)NCH * 64 * TH0 * 16];
__device__ __align__(128) __half  g_loA[(size_t)NCH * 64 * TH0 * 16];
__device__ __align__(128) __half  g_hiB[(size_t)NCH * 64 * TH1 * 16];
__device__ __align__(128) __half  g_loB[(size_t)NCH * 64 * TH1 * 16];
__device__ __align__(128) float   g_c5 [(size_t)NCH * D_ * T_];
__device__ __align__(128) __half  g_wh[14 * WSL];

// ---------------- helpers ----------------
__device__ __forceinline__ float gelu_exact(float v) {
    return 0.5f * v * (1.0f + erff(v * 0.70710678118654752f));
}
__device__ __forceinline__ uint32_t s2u(const void* p) {
    uint32_t a;
    asm("{ .reg .u64 t; cvta.to.shared.u64 t, %1; cvt.u32.u64 %0, t; }" : "=r"(a) : "l"(p));
    return a;
}
__device__ __forceinline__ void mb_init(uint32_t a, uint32_t c) {
    asm volatile("mbarrier.init.shared.b64 [%0], %1;" :: "r"(a), "r"(c) : "memory");
}
__device__ __forceinline__ void mb_expect(uint32_t a, uint32_t bytes) {
    asm volatile("mbarrier.arrive.expect_tx.shared.b64 _, [%0], %1;" :: "r"(a), "r"(bytes) : "memory");
}
__device__ __forceinline__ void mb_arrive(uint32_t a) {
    asm volatile("mbarrier.arrive.shared.b64 _, [%0];" :: "r"(a) : "memory");
}
__device__ __forceinline__ void mb_wait(uint32_t a, uint32_t par) {
    asm volatile("{\n\t.reg .pred P;\n\tWL%=:\n\t"
                 "mbarrier.try_wait.parity.acquire.cta.shared::cta.b64 P, [%0], %1, 0x989680;\n\t"
                 "@!P bra WL%=;\n\t}" :: "r"(a), "r"(par) : "memory");
}
__device__ __forceinline__ void bulk_cp(uint32_t dst, const void* src, uint32_t sz, uint32_t mb) {
    asm volatile("cp.async.bulk.shared::cta.global.mbarrier::complete_tx::bytes [%0], [%1], %2, [%3];"
                 :: "r"(dst), "l"(src), "r"(sz), "r"(mb) : "memory");
}
#define FENCE_ASYNC() asm volatile("fence.proxy.async.shared::cta;" ::: "memory")
__device__ __forceinline__ void ldsm4(uint32_t* r, uint32_t a) {
    asm volatile("ldmatrix.sync.aligned.m8n8.x4.shared.b16 {%0,%1,%2,%3}, [%4];"
                 : "=r"(r[0]), "=r"(r[1]), "=r"(r[2]), "=r"(r[3]) : "r"(a));
}
__device__ __forceinline__ void mma_f16(float* c, const uint32_t* a, uint32_t b0, uint32_t b1) {
    asm volatile("mma.sync.aligned.m16n8k16.row.col.f32.f16.f16.f32 "
        "{%0,%1,%2,%3}, {%4,%5,%6,%7}, {%8,%9}, {%0,%1,%2,%3};"
        : "+f"(c[0]), "+f"(c[1]), "+f"(c[2]), "+f"(c[3])
        : "r"(a[0]), "r"(a[1]), "r"(a[2]), "r"(a[3]), "r"(b0), "r"(b1));
}

// act address (bytes) for element (n, plane value cv, phys index i)
__device__ __forceinline__ size_t act_off(int n, int cv, int i, int Th) {
    int row = i >> 1, p = i & 1;
    int c = cv >> 4, g = (cv >> 3) & 1;
    int sw = g ^ ((row >> 2) & 1);
    return (((size_t)(n * 32 + c) * 2 + p) * Th + row) * 32 + sw * 16 + (cv & 7) * 2;
}

// ---------- fused conv0 + GroupNorm + GELU (sliding-window; hi plane only) ----------
__global__ __launch_bounds__(256) void conv0_fused(
    const float* __restrict__ x, const float* __restrict__ W0,
    const float* __restrict__ g0, const float* __restrict__ b0,
    __half* __restrict__ hi)
{
    __shared__ float xs[L_IN + 8];
    __shared__ float r1[8][32], r2[8][32];
    const int n = blockIdx.y, tid = threadIdx.x;
    const int lane = tid & 31, wid = tid >> 5;
    const int co = blockIdx.x * 32 + lane;

    float w[10];
#pragma unroll
    for (int k = 0; k < 10; ++k) w[k] = W0[co * 10 + k];
    const float* xr = x + (size_t)n * L_IN;
    for (int i = tid; i < L_IN; i += 256) xs[i] = xr[i];
    if (tid < 8) xs[L_IN + tid] = 0.f;
    __syncthreads();

    const int CH   = (L0_ + 7) / 8;
    const int tbeg = wid * CH;
    const int tend = (tbeg + CH < L0_) ? (tbeg + CH) : L0_;

    float lsum = 0.f, lsq = 0.f;
    {
        float xw[10];
#pragma unroll
        for (int j = 0; j < 10; ++j) xw[j] = xs[3 * tbeg + j];
        for (int t = tbeg; t < tend; ++t) {
            float s = 0.f;
#pragma unroll
            for (int k = 0; k < 10; ++k) s += xw[k] * w[k];
            lsum += s; lsq += s * s;
#pragma unroll
            for (int j = 0; j < 7; ++j) xw[j] = xw[j + 3];
            xw[7] = xs[3 * t + 10]; xw[8] = xs[3 * t + 11]; xw[9] = xs[3 * t + 12];
        }
    }
    r1[wid][lane] = lsum; r2[wid][lane] = lsq;
    __syncthreads();
    float tot = 0.f, tsq = 0.f;
#pragma unroll
    for (int i = 0; i < 8; ++i) { tot += r1[i][lane]; tsq += r2[i][lane]; }
    const float mu  = tot * (1.0f / L0_);
    const float var = tsq * (1.0f / L0_) - mu * mu;
    const float sc  = rsqrtf(var + 1e-5f) * g0[co];
    const float sh  = b0[co] - mu * sc;

    {
        float xw[10];
#pragma unroll
        for (int j = 0; j < 10; ++j) xw[j] = xs[3 * tbeg + j];
        for (int t = tbeg; t < tend; ++t) {
            float s = 0.f;
#pragma unroll
            for (int k = 0; k < 10; ++k) s += xw[k] * w[k];
            float v = gelu_exact(s * sc + sh);
            size_t off = act_off(n, co, t, TH0);
            *(__half*)((char*)hi + off) = __float2half(v);
#pragma unroll
            for (int j = 0; j < 7; ++j) xw[j] = xw[j + 3];
            xw[7] = xs[3 * t + 10]; xw[8] = xs[3 * t + 11]; xw[9] = xs[3 * t + 12];
        }
    }
}

// ---------- ALL weights fp32 [co][ci][kw] -> single fp16 swizzled tiles ----------
__global__ void prep_w_all(
    const float* __restrict__ W1, const float* __restrict__ W2,
    const float* __restrict__ W3, const float* __restrict__ W4,
    const float* __restrict__ W5, __half* __restrict__ wh)
{
    int idx = blockIdx.x * 256 + threadIdx.x;
    if (idx >= 14 * WSL) return;
    int s = idx >> 18, r = idx & (WSL - 1);
    int co = r >> 9, ci = r & 511;
    const float* W; int k, KW;
    if      (s < 3)  { W = W1; k = s;      KW = 3; }
    else if (s < 6)  { W = W2; k = s - 3;  KW = 3; }
    else if (s < 9)  { W = W3; k = s - 6;  KW = 3; }
    else if (s < 12) { W = W4; k = s - 9;  KW = 3; }
    else             { W = W5; k = s - 12; KW = 2; }
    float v = W[(size_t)(co * 512 + ci) * KW + k];
    int sw = ((ci >> 3) & 1) ^ ((co >> 2) & 1);
    size_t off = ((size_t)(s * 32 + (ci >> 4)) * 512 + co) * 32 + sw * 16 + (ci & 7) * 2;
    *(__half*)((char*)wh + off) = __float2half(v);
}

// ---------- conv layer: 3-deep bulk pipeline, fp16 HMMA (1 or 2 act terms) ----------
// CTA 128co x NTt, 8 warps 4m x 2n (warp 32co x NT/2 t). 32 stages of ci16.
// Dynamic smem >= max(3*BUF+48, NT*544).
template<int KW, int NT, bool FP32OUT, bool HASLO>
__global__ __launch_bounds__(256, 2) void conv_bulk(
    const __half* __restrict__ xh, const __half* __restrict__ xl,
    const __half* __restrict__ wt,
    void* __restrict__ outA, __half* __restrict__ outLo,
    int Lin, int Lout, int ThIn, int ThOut)
{
    extern __shared__ __align__(128) char smem[];
    constexpr int ROWS_E = NT + (KW == 3 ? 1 : 0);
    constexpr int ROWS_O = NT;
    constexpr int OFF_B  = KW * 4096;
    constexpr int BUF    = OFF_B + 2 * (ROWS_E + ROWS_O) * 32;
    constexpr int NN     = NT / 16;
    constexpr int NB     = NT / 32;
    const int tid = threadIdx.x, lane = tid & 31, wid = tid >> 5;
    const int wm = wid >> 1, wn = wid & 1;
    const int n = blockIdx.z, co0 = blockIdx.y * 128, t0 = blockIdx.x * NT;
    const uint32_t sb  = s2u(smem);
    const uint32_t mbF = sb + 3 * BUF;
    const uint32_t mbE = mbF + 24;

    float acc[2][NN][4];
#pragma unroll
    for (int m = 0; m < 2; ++m)
#pragma unroll
        for (int nn = 0; nn < NN; ++nn)
#pragma unroll
            for (int i = 0; i < 4; ++i) acc[m][nn][i] = 0.f;

    auto load_stage = [&](int s, int slot) {
        const uint32_t bufb = sb + (uint32_t)slot * BUF;
        const uint32_t mb = mbF + (uint32_t)slot * 8;
        const uint32_t actb = (HASLO ? 2u : 1u) * (uint32_t)((ROWS_E + ROWS_O) * 32);
        mb_expect(mb, (uint32_t)(KW * 4096) + actb);
#pragma unroll
        for (int k = 0; k < KW; ++k) {
            size_t wo = ((size_t)(k * 32 + s) * 512 + co0) * 32;
            bulk_cp(bufb + k * 4096, (const char*)wt + wo, 4096, mb);
        }
        size_t be = (((size_t)(n * 32 + s) * 2 + 0) * ThIn + t0) * 32;
        size_t bo = (((size_t)(n * 32 + s) * 2 + 1) * ThIn + t0) * 32;
        bulk_cp(bufb + OFF_B,                     (const char*)xh + be, ROWS_E * 32, mb);
        bulk_cp(bufb + OFF_B + 2 * ROWS_E * 32,   (const char*)xh + bo, ROWS_O * 32, mb);
        if (HASLO) {
            bulk_cp(bufb + OFF_B + ROWS_E * 32,                   (const char*)xl + be, ROWS_E * 32, mb);
            bulk_cp(bufb + OFF_B + 2 * ROWS_E * 32 + ROWS_O * 32, (const char*)xl + bo, ROWS_O * 32, mb);
        }
    };

    if (tid == 0) {
#pragma unroll
        for (int i = 0; i < 3; ++i) { mb_init(mbF + 8 * i, 1); mb_init(mbE + 8 * i, 8); }
    }
    __syncthreads();
    if (tid == 0) { FENCE_ASYNC(); load_stage(0, 0); load_stage(1, 1); load_stage(2, 2); }

    const int laneR = lane & 15, gsel = lane >> 4;
    int slot = 0, fph = 0;
    for (int s = 0; s < 32; ++s) {
        mb_wait(mbF + 8u * slot, fph);
        const uint32_t bufb = sb + (uint32_t)slot * BUF;

        auto baddr = [&](int k, int b) -> uint32_t {
            const int p = k & 1, kd = k >> 1;
            const uint32_t baseh = bufb + OFF_B + (p ? 2 * ROWS_E * 32 : 0);
            int r = wn * (NT / 2) + b * 16 + laneR + kd;
            return baseh + r * 32 + ((gsel ^ ((r >> 2) & 1)) << 4);
        };

        uint32_t bh[2][4], bl[2][4];
        {
            uint32_t a = baddr(0, 0);
            ldsm4(bh[0], a);
            if (HASLO) ldsm4(bl[0], a + ROWS_E * 32);
        }
        int cur = 0;
#pragma unroll
        for (int k = 0; k < KW; ++k) {
            uint32_t ah[2][4];
#pragma unroll
            for (int m = 0; m < 2; ++m) {
                int r = wm * 32 + m * 16 + laneR;
                uint32_t a = bufb + k * 4096 + r * 32 + ((gsel ^ ((r >> 2) & 1)) << 4);
                ldsm4(ah[m], a);
            }
#pragma unroll
            for (int b = 0; b < NB; ++b) {
                const int nk = (b + 1 < NB) ? k : k + 1;
                const int nb = (b + 1 < NB) ? b + 1 : 0;
                if (nk < KW) {
                    uint32_t a = baddr(nk, nb);
                    ldsm4(bh[cur ^ 1], a);
                    if (HASLO) {
                        uint32_t rs = ((nk & 1) ? ROWS_O : ROWS_E) * 32;
                        ldsm4(bl[cur ^ 1], a + rs);
                    }
                }
                const uint32_t* BH = bh[cur];
#pragma unroll
                for (int m = 0; m < 2; ++m)
#pragma unroll
                    for (int o = 0; o < 2; ++o)
                        mma_f16(acc[m][b * 2 + o], ah[m], BH[o], BH[o + 2]);
                if (HASLO) {
                    const uint32_t* BL = bl[cur];
#pragma unroll
                    for (int m = 0; m < 2; ++m)
#pragma unroll
                        for (int o = 0; o < 2; ++o)
                            mma_f16(acc[m][b * 2 + o], ah[m], BL[o], BL[o + 2]);
                }
                cur ^= 1;
            }
        }
        __syncwarp();
        if (lane == 0) mb_arrive(mbE + 8u * slot);
        if (tid == 0 && s + 3 < 32) {
            mb_wait(mbE + 8u * slot, (uint32_t)((s / 3) & 1));
            load_stage(s + 3, slot);
        }
        if (++slot == 3) { slot = 0; fph ^= 1; }
    }
    __syncthreads();

    if (FP32OUT) {
        float* outF = (float*)outA;
#pragma unroll
        for (int m = 0; m < 2; ++m) {
            const int coA = co0 + wm * 32 + m * 16 + (lane >> 2);
#pragma unroll
            for (int nn = 0; nn < NN; ++nn) {
                int tt = t0 + wn * (NT / 2) + nn * 8 + 2 * (lane & 3);
#pragma unroll
                for (int i = 0; i < 4; ++i) {
                    int t = tt + (i & 1), co = coA + (i >> 1) * 8;
                    if (t < Lout)
                        outF[((size_t)n * D_ + co) * T_ + t] = gelu_exact(acc[m][nn][i]);
                }
            }
        }
    } else {
        __half* sHi = (__half*)smem;
        __half* sLo = (__half*)(smem + NT * 272);
#pragma unroll
        for (int m = 0; m < 2; ++m) {
            const int coA = wm * 32 + m * 16 + (lane >> 2);
#pragma unroll
            for (int nn = 0; nn < NN; ++nn) {
                const int tt = wn * (NT / 2) + nn * 8 + 2 * (lane & 3);
#pragma unroll
                for (int i = 0; i < 4; ++i) {
                    int t = tt + (i & 1), co = coA + (i >> 1) * 8;
                    float g = gelu_exact(acc[m][nn][i]);
                    __half h = __float2half(g);
                    sHi[t * 136 + co] = h;
                    sLo[t * 136 + co] = __float2half(g - __half2float(h));
                }
            }
        }
        __syncthreads();
        for (int idx = tid; idx < NT * 16; idx += 256) {
            int t = idx >> 4, gg = idx & 15;
            int tAbs = t0 + t;
            if (tAbs < Lout) {
                int row = tAbs >> 1, p = tAbs & 1;
                int coA = co0 + gg * 8;
                int c = coA >> 4, gb = (coA >> 3) & 1;
                int sw = gb ^ ((row >> 2) & 1);
                size_t off = (((size_t)(n * 32 + c) * 2 + p) * ThOut + row) * 32 + sw * 16;
                *(uint4*)((char*)outA + off) = *(uint4*)(smem + t * 272 + gg * 16);
                if (outLo)
                    *(uint4*)((char*)outLo + off) = *(uint4*)(smem + NT * 272 + t * 272 + gg * 16);
            }
        }
    }
}

// ---------- 1x1 channel fusion ----------
__global__ void fusion_kernel(const float* __restrict__ h, const float* __restrict__ fw,
                              const float* __restrict__ fb, float* __restrict__ ze)
{
    int idx = blockIdx.x * 256 + threadIdx.x;
    if (idx >= SECT) return;
    int b = idx / (D_ * T_);
    int r = idx - b * (D_ * T_);
    float s = fb[0];
    const float* hp = h + (size_t)b * C_ * D_ * T_ + r;
#pragma unroll 5
    for (int c = 0; c < C_; ++c) s += hp[(size_t)c * D_ * T_] * fw[c];
    ze[idx] = s;
}

// ---------- VQ argmin ----------
__global__ __launch_bounds__(256) void quantize_kernel(
    const float* __restrict__ ze, const float* __restrict__ cb, float* __restrict__ out)
{
    __shared__ __align__(16) float z[512];
    __shared__ float sd[256];
    __shared__ int   si[256];
    const int blk = blockIdx.x;
    const int b = blk / T_, t = blk - b * T_;
    const int tid = threadIdx.x;

    const float* zb = ze + (size_t)b * D_ * T_ + t;
    for (int d = tid; d < D_; d += 256) z[d] = zb[(size_t)d * T_];
    __syncthreads();

    float best = 3.4e38f; int bi = 0;
    for (int kk = tid; kk < KCODES; kk += 256) {
        const float4* cr = reinterpret_cast<const float4*>(cb + (size_t)kk * D_);
        const float4* zr = reinterpret_cast<const float4*>(z);
        float s = 0.f;
#pragma unroll 8
        for (int q = 0; q < 128; ++q) {
            float4 c4 = cr[q], z4 = zr[q];
            float d0 = z4.x - c4.x, d1 = z4.y - c4.y;
            float d2 = z4.z - c4.z, d3 = z4.w - c4.w;
            s += d0 * d0 + d1 * d1 + d2 * d2 + d3 * d3;
        }
        if (s < best) { best = s; bi = kk; }
    }
    sd[tid] = best; si[tid] = bi;
    __syncthreads();
    for (int off = 128; off; off >>= 1) {
        if (tid < off) {
            float od = sd[tid + off]; int oi = si[tid + off];
            if (od < sd[tid] || (od == sd[tid] && oi < si[tid])) { sd[tid] = od; si[tid] = oi; }
        }
        __syncthreads();
    }
    const int w = si[0];
    const float* crow = cb + (size_t)w * D_;
    const size_t base = (size_t)b * D_ * T_ + t;
    for (int d = tid; d < D_; d += 256) {
        float v = crow[d];
        out[base + (size_t)d * T_]            = v;
        out[2 * SECT + base + (size_t)d * T_] = v;
    }
}

// ---------- launch ----------
extern "C" void kernel_launch(void* const* d_in, const int* in_sizes, int n_in,
                              void* d_out, int out_size)
{
    const float* x  = (const float*)d_in[0];
    const float* W0 = (const float*)d_in[4];
    const float* g0 = (const float*)d_in[5];
    const float* b0 = (const float*)d_in[6];
    const float* W1 = (const float*)d_in[7];
    const float* W2 = (const float*)d_in[8];
    const float* W3 = (const float*)d_in[9];
    const float* W4 = (const float*)d_in[10];
    const float* W5 = (const float*)d_in[11];
    const float* fw = (const float*)d_in[12];
    const float* fb = (const float*)d_in[13];
    const float* cb = (const float*)d_in[14];
    float* out = (float*)d_out;

    float* pc5 = nullptr;
    __half *hA, *lA, *hB, *lB, *wh;
    cudaGetSymbolAddress((void**)&pc5, g_c5);
    cudaGetSymbolAddress((void**)&hA,  g_hiA);
    cudaGetSymbolAddress((void**)&lA,  g_loA);
    cudaGetSymbolAddress((void**)&hB,  g_hiB);
    cudaGetSymbolAddress((void**)&lB,  g_loB);
    cudaGetSymbolAddress((void**)&wh,  g_wh);

    const int SM160 = 3 * (3 * 4096 + 2 * (161 + 160) * 32) + 48;  // 98544 > 87040 retile
    const int SM128 = 3 * (3 * 4096 + 2 * (129 + 128) * 32) + 48;  // 86256 > 69632 retile
    const int SM64  = 3 * (2 * 4096 + 2 * (64 + 64) * 32) + 48;    // 49200
    cudaFuncSetAttribute(conv_bulk<3, 160, false, false>, cudaFuncAttributeMaxDynamicSharedMemorySize, SM160);
    cudaFuncSetAttribute(conv_bulk<3, 128, false, true>,  cudaFuncAttributeMaxDynamicSharedMemorySize, SM128);
    cudaFuncSetAttribute(conv_bulk<2, 64, true, true>,    cudaFuncAttributeMaxDynamicSharedMemorySize, SM64);

    prep_w_all<<<(14 * WSL + 255) / 256, 256>>>(W1, W2, W3, W4, W5, wh);
    conv0_fused<<<dim3(16, NCH), 256>>>(x, W0, g0, b0, hA);

    // conv1, conv2: single-term (acts fp16-rounded); conv3..5: two-term
    conv_bulk<3, 160, false, false><<<dim3(6, 4, NCH), 256, SM160>>>(hA, nullptr, wh + 0 * WSL, hB, nullptr, 1831, 915, TH0, TH1);
    conv_bulk<3, 160, false, false><<<dim3(3, 4, NCH), 256, SM160>>>(hB, nullptr, wh + 3 * WSL, hA, lA, 915, 457, TH1, TH2);
    conv_bulk<3, 128, false, true><<<dim3(2, 4, NCH), 256, SM128>>>(hA, lA, wh + 6 * WSL, hB, lB, 457, 228, TH2, TH3);
    conv_bulk<3, 128, false, true><<<dim3(1, 4, NCH), 256, SM128>>>(hB, lB, wh + 9 * WSL, hA, lA, 228, 113, TH3, TH4);
    conv_bulk<2, 64, true, true><<<dim3(1, 4, NCH), 256, SM64>>>(hA, lA, wh + 12 * WSL, pc5, nullptr, 113, 56, TH4, 0);

    fusion_kernel<<<(SECT + 255) / 256, 256>>>(pc5, fw, fb, out + SECT);
    quantize_kernel<<<B_ * T_, 256>>>(out + SECT, cb, out);
}